// round 6
// baseline (speedup 1.0000x reference)
#include <cuda_runtime.h>
#include <cstdint>

// LoRIExpertBank as a single NT GEMM (tcgen05 unavailable: harness PTX targets
// base sm_103, which rejects tcgen05/TMEM — verified by ptxas error R4).
//   out[t,d] = sum_c Q[t,c] * Aflat[d,c],  c = k*64 + r,  Q[t,c] = w[t,k]*p[t,r]
// T=16384, D=4096, K=8, R=64. SCALING = 64/64 = 1. A pre-masked in setup =>
// sparse_mask ignored (bitwise no-op). tf32 mma.sync, fp32 accumulate.
//
// R5 change vs R1 baseline (620.7us): __launch_bounds__(256, 2) => 2 CTAs/SM
// (regs capped 128, smem 33KB*2=66KB). R1 was latency-bound: occ 12.5%,
// issue 44.6%, L1 61.6% (unsaturated). Doubling warps/SMSP 2->4 targets issue.

#define BM 128
#define BN 128
#define BK 16
#define KC 512
#define TOK 16384
#define DIM 4096
#define NIT (KC / BK)   // 32

__device__ __forceinline__ uint32_t f2tf32(float x) {
    uint32_t u;
    asm("cvt.rna.tf32.f32 %0, %1;" : "=r"(u) : "f"(x));
    return u;
}

__device__ __forceinline__ void mma_tf32(float c[4],
                                         uint32_t a0, uint32_t a1, uint32_t a2, uint32_t a3,
                                         uint32_t b0, uint32_t b1) {
    asm volatile(
        "mma.sync.aligned.m16n8k8.row.col.f32.tf32.tf32.f32 "
        "{%0,%1,%2,%3}, {%4,%5,%6,%7}, {%8,%9}, {%0,%1,%2,%3};"
        : "+f"(c[0]), "+f"(c[1]), "+f"(c[2]), "+f"(c[3])
        : "r"(a0), "r"(a1), "r"(a2), "r"(a3), "r"(b0), "r"(b1));
}

// smem layout per tile: [row][16] floats (64B rows).
// k-permutation: k = j*8 + c, c = tg + 4h  ->  pos = tg*4 + j*2 + h
//   (each mma-thread's BK=16 fragment is one contiguous float4)
// XOR swizzle: float-pos ^= ((row>>1)&3)*4  -> conflict-free LDS.128 and STS.32.

__global__ __launch_bounds__(256, 2)
void lori_gemm_tf32(const float* __restrict__ P,   // [TOK, 64]
                    const float* __restrict__ W,   // [TOK, 8]
                    const float* __restrict__ A,   // [8, 4096, 64]
                    float* __restrict__ OUT)       // [TOK, 4096]
{
    __shared__ float Qs[2][BM * BK];
    __shared__ float As[2][BN * BK];

    const int tid  = threadIdx.x;
    const int lane = tid & 31;
    const int warp = tid >> 5;
    const int g    = lane >> 2;   // 0..7
    const int tg   = lane & 3;    // 0..3
    const int wm   = warp >> 1;   // 0..3  (M band of 32)
    const int wn   = warp & 1;    // 0..1  (N band of 64)
    const int mBase = blockIdx.y * BM;
    const int nBase = blockIdx.x * BN;
    const int lrow = tid >> 2;    // 0..63 (load row)
    const int lm4  = tid & 3;     // which float4 within a 16-float row

    // precomputed global bases (help ptxas keep addressing lean)
    const float* Pb = P + (size_t)(mBase + lrow) * 64 + lm4 * 4;
    const float* Wb = W + (size_t)(mBase + lrow) * 8;
    const float* Ab = A + (size_t)(nBase + lrow) * 64 + lm4 * 4;

    float acc[2][8][4];
    #pragma unroll
    for (int mi = 0; mi < 2; ++mi)
        #pragma unroll
        for (int ni = 0; ni < 8; ++ni)
            #pragma unroll
            for (int e = 0; e < 4; ++e) acc[mi][ni][e] = 0.0f;

    float4 qv[2];  // raw p float4 per staged row
    float  wv[2];  // routing weight per staged row
    float4 av[2];  // raw A float4 per staged row

    auto load_iter = [&](int kb) {
        const int ke = kb >> 2;              // expert index
        const int r0 = (kb & 3) * BK;        // rank offset within expert
        #pragma unroll
        for (int rr = 0; rr < 2; ++rr) {
            qv[rr] = *reinterpret_cast<const float4*>(Pb + (size_t)(rr * 64) * 64 + r0);
            wv[rr] = Wb[(size_t)(rr * 64) * 8 + ke];
            av[rr] = *reinterpret_cast<const float4*>(
                Ab + (size_t)ke * (DIM * 64) + (size_t)(rr * 64) * 64 + r0);
        }
    };

    auto sts_iter = [&](int b) {
        #pragma unroll
        for (int rr = 0; rr < 2; ++rr) {
            const int row = lrow + rr * 64;
            const int s   = ((row >> 1) & 3) * 4;
            float* q = &Qs[b][row * BK];
            float* a = &As[b][row * BK];
            float qx[4] = { qv[rr].x * wv[rr], qv[rr].y * wv[rr],
                            qv[rr].z * wv[rr], qv[rr].w * wv[rr] };
            float ax[4] = { av[rr].x, av[rr].y, av[rr].z, av[rr].w };
            #pragma unroll
            for (int i = 0; i < 4; ++i) {
                const int pos = (i * 4 + lm4) ^ s;   // k-perm: global k = lm4*4 + i
                q[pos] = __uint_as_float(f2tf32(qx[i]));
                a[pos] = __uint_as_float(f2tf32(ax[i]));
            }
        }
    };

    auto compute = [&](int b) {
        // A-operand (Q) fragments: 2 mtiles x 2 rows, each one LDS.128
        uint32_t aq[2][2][4];
        #pragma unroll
        for (int mi = 0; mi < 2; ++mi)
            #pragma unroll
            for (int rr = 0; rr < 2; ++rr) {
                const int arow = wm * 32 + mi * 16 + rr * 8 + g;
                const int s    = ((arow >> 1) & 3) * 4;
                float4 v = *reinterpret_cast<const float4*>(
                    &Qs[b][arow * BK + ((tg * 4) ^ s)]);
                aq[mi][rr][0] = __float_as_uint(v.x);
                aq[mi][rr][1] = __float_as_uint(v.y);
                aq[mi][rr][2] = __float_as_uint(v.z);
                aq[mi][rr][3] = __float_as_uint(v.w);
            }
        #pragma unroll
        for (int ni = 0; ni < 8; ++ni) {
            const int brow = wn * 64 + ni * 8 + g;
            const int s    = ((brow >> 1) & 3) * 4;
            float4 v = *reinterpret_cast<const float4*>(
                &As[b][brow * BK + ((tg * 4) ^ s)]);
            const uint32_t b0 = __float_as_uint(v.x);
            const uint32_t b1 = __float_as_uint(v.y);
            const uint32_t b2 = __float_as_uint(v.z);
            const uint32_t b3 = __float_as_uint(v.w);
            #pragma unroll
            for (int mi = 0; mi < 2; ++mi) {
                // kstep 0: quad elements {x=(k0,tg), y=(k0,tg+4)}
                mma_tf32(acc[mi][ni],
                         aq[mi][0][0], aq[mi][1][0], aq[mi][0][1], aq[mi][1][1],
                         b0, b1);
                // kstep 1: quad elements {z=(k1,tg), w=(k1,tg+4)}
                mma_tf32(acc[mi][ni],
                         aq[mi][0][2], aq[mi][1][2], aq[mi][0][3], aq[mi][1][3],
                         b2, b3);
            }
        }
    };

    // Pipeline: double-buffered smem, global loads for it+1 issued before compute(it)
    load_iter(0);
    sts_iter(0);
    __syncthreads();

    #pragma unroll 1
    for (int it = 0; it < NIT; ++it) {
        const int b = it & 1;
        if (it + 1 < NIT) load_iter(it + 1);
        compute(b);
        if (it + 1 < NIT) sts_iter(1 - b);
        __syncthreads();
    }

    // Epilogue: c0,c1 -> (row g, cols 2tg,2tg+1); c2,c3 -> row g+8. float2 stores,
    // each 8-lane g-group covers one full 32B sector.
    #pragma unroll
    for (int mi = 0; mi < 2; ++mi)
        #pragma unroll
        for (int rr = 0; rr < 2; ++rr) {
            const int row = mBase + wm * 32 + mi * 16 + rr * 8 + g;
            float* o = OUT + (size_t)row * DIM + nBase + wn * 64 + tg * 2;
            #pragma unroll
            for (int ni = 0; ni < 8; ++ni) {
                float2 v = make_float2(acc[mi][ni][rr * 2], acc[mi][ni][rr * 2 + 1]);
                *reinterpret_cast<float2*>(o + ni * 8) = v;
            }
        }
}

extern "C" void kernel_launch(void* const* d_in, const int* in_sizes, int n_in,
                              void* d_out, int out_size) {
    const float* P = (const float*)d_in[0];  // projected_input [4,4096,64]
    const float* W = (const float*)d_in[1];  // routing_weights [4,4096,8]
    const float* A = (const float*)d_in[2];  // A [8,4096,64] (pre-masked)
    // d_in[3] (sparse_mask) unused: A = A*mask already applied in setup;
    // mask is binary so re-masking is an exact no-op.
    (void)in_sizes; (void)n_in; (void)out_size;
    float* OUT = (float*)d_out;

    dim3 grid(DIM / BN, TOK / BM);   // (32, 128); x-fastest keeps A + Q band in L2
    lori_gemm_tf32<<<grid, 256>>>(P, W, A, OUT);
}

// round 10
// speedup vs baseline: 2.4173x; 2.4173x over previous
#include <cuda_runtime.h>
#include <cuda_fp16.h>
#include <cstdint>

// LoRIExpertBank as one NT GEMM, fp16 operands / fp32 accum (mma.m16n8k16).
//   out[t,d] = sum_c Q[t,c] * Aflat[d,c],  c = k*64+r,  Q[t,c] = w[t,k]*p[t,r]
// T=16384 (M), D=4096 (N), C=512 (K). SCALING = 64/64 = 1. A pre-masked in
// setup => sparse_mask ignored. fp16 has an 11-bit significand == tf32, so
// accuracy matches the validated tf32 path (~2.9e-4) at 2x MAC rate and half
// the smem bytes. tcgen05 unavailable (harness PTX targets base sm_103).
//
// Pipeline: prep_q / prep_a convert+permute operands into __device__ buffers
// (fragment-ordered, so the mainloop is pure cp.async -> LDS.128 -> HMMA).
// Main: CTA 128x256, 8 warps as 2x4, warp tile 64x64 (32 B LDS per output),
// 3-stage cp.async ring (24KB/stage), 16 K-chunks of 32 halves (64B rows).

#define TOK 16384
#define DIM 4096
#define BM  128
#define BN  256
#define NIT 16
#define STAGE_BYTES 24576            // 8KB Q + 16KB A
#define SMEM_BYTES (3 * STAGE_BYTES) // 73728

// Operand buffers, fragment-permuted fp16. Row = 512 halves = 1024B = 64 uint4.
__device__ __align__(16) uint4 QH[(size_t)TOK * 64];   // 16 MB
__device__ __align__(16) uint4 AH[(size_t)DIM * 64];   //  4 MB

// Within each 32-half K-chunk, half-pair hp (0..15) is stored at slot
// pos = (hp&3)*4 + (hp>>2)  (involutive digit swap). Lane tg of an mma quad
// then reads its whole k16x2 fragment {hp = tg, tg+4, tg+8, tg+12} as ONE
// contiguous 16B chunk (chunk index = tg), XOR-swizzled by ((row>>1)&3).

__global__ void prep_q(const float* __restrict__ P,   // [TOK, 64]
                       const float* __restrict__ W) { // [TOK, 8]
    const int idx = blockIdx.x * 256 + threadIdx.x;   // TOK*16
    const int t  = idx >> 4;
    const int kb = idx & 15;                          // 32-half chunk
    const float w = W[t * 8 + (kb >> 1)];             // expert = kb/2
    const float4* src = reinterpret_cast<const float4*>(
        P + (size_t)t * 64 + (kb & 1) * 32);
    float f[32];
    #pragma unroll
    for (int i = 0; i < 8; ++i) {
        float4 v = src[i];
        f[i*4+0] = v.x; f[i*4+1] = v.y; f[i*4+2] = v.z; f[i*4+3] = v.w;
    }
    uint32_t o[16];
    #pragma unroll
    for (int pos = 0; pos < 16; ++pos) {
        const int hp = ((pos & 3) << 2) | (pos >> 2);
        __half2 h = __floats2half2_rn(w * f[2*hp], w * f[2*hp+1]);
        o[pos] = *reinterpret_cast<uint32_t*>(&h);
    }
    uint4* dst = QH + (size_t)t * 64 + kb * 4;
    dst[0] = make_uint4(o[0],  o[1],  o[2],  o[3]);
    dst[1] = make_uint4(o[4],  o[5],  o[6],  o[7]);
    dst[2] = make_uint4(o[8],  o[9],  o[10], o[11]);
    dst[3] = make_uint4(o[12], o[13], o[14], o[15]);
}

__global__ void prep_a(const float* __restrict__ A) { // [8, 4096, 64]
    const int idx = blockIdx.x * 256 + threadIdx.x;   // DIM*16
    const int d  = idx >> 4;
    const int kb = idx & 15;
    const float4* src = reinterpret_cast<const float4*>(
        A + ((size_t)(kb >> 1) * DIM + d) * 64 + (kb & 1) * 32);
    float f[32];
    #pragma unroll
    for (int i = 0; i < 8; ++i) {
        float4 v = src[i];
        f[i*4+0] = v.x; f[i*4+1] = v.y; f[i*4+2] = v.z; f[i*4+3] = v.w;
    }
    uint32_t o[16];
    #pragma unroll
    for (int pos = 0; pos < 16; ++pos) {
        const int hp = ((pos & 3) << 2) | (pos >> 2);
        __half2 h = __floats2half2_rn(f[2*hp], f[2*hp+1]);
        o[pos] = *reinterpret_cast<uint32_t*>(&h);
    }
    uint4* dst = AH + (size_t)d * 64 + kb * 4;
    dst[0] = make_uint4(o[0],  o[1],  o[2],  o[3]);
    dst[1] = make_uint4(o[4],  o[5],  o[6],  o[7]);
    dst[2] = make_uint4(o[8],  o[9],  o[10], o[11]);
    dst[3] = make_uint4(o[12], o[13], o[14], o[15]);
}

__device__ __forceinline__ void mma_f16(float c[4],
                                        uint32_t a0, uint32_t a1, uint32_t a2, uint32_t a3,
                                        uint32_t b0, uint32_t b1) {
    asm volatile(
        "mma.sync.aligned.m16n8k16.row.col.f32.f16.f16.f32 "
        "{%0,%1,%2,%3}, {%4,%5,%6,%7}, {%8,%9}, {%0,%1,%2,%3};"
        : "+f"(c[0]), "+f"(c[1]), "+f"(c[2]), "+f"(c[3])
        : "r"(a0), "r"(a1), "r"(a2), "r"(a3), "r"(b0), "r"(b1));
}

__global__ __launch_bounds__(256, 1)
void lori_h16(float* __restrict__ OUT) {
    extern __shared__ char smem[];
    const uint32_t sb = (uint32_t)__cvta_generic_to_shared(smem);
    const int tid  = threadIdx.x;
    const int lane = tid & 31;
    const int warp = tid >> 5;
    const int g  = lane >> 2;     // 0..7
    const int tg = lane & 3;      // 0..3
    const int wm = warp >> 2;     // 0..1 (M band of 64)
    const int wn = warp & 3;      // 0..3 (N band of 64)
    const int mBase = blockIdx.y * BM;
    const int nBase = blockIdx.x * BN;

    const char* Qg = reinterpret_cast<const char*>(QH) + (size_t)mBase * 1024;
    const char* Ag = reinterpret_cast<const char*>(AH) + (size_t)nBase * 1024;

    auto issue_copy = [&](int kb, int stg) {
        const uint32_t qb = sb + stg * STAGE_BYTES;
        const uint32_t ab = qb + 8192;
        // Q: 512 16B chunks (128 rows x 4), A: 1024 chunks (256 rows x 4)
        #pragma unroll
        for (int j = 0; j < 2; ++j) {
            const int cid = tid + j * 256;
            const int row = cid >> 2, i = cid & 3;
            const uint32_t dst = qb + row * 64 + ((i ^ ((row >> 1) & 3)) << 4);
            const char* src = Qg + (size_t)row * 1024 + kb * 64 + i * 16;
            asm volatile("cp.async.cg.shared.global [%0], [%1], 16;"
                         :: "r"(dst), "l"(src) : "memory");
        }
        #pragma unroll
        for (int j = 0; j < 4; ++j) {
            const int cid = tid + j * 256;
            const int row = cid >> 2, i = cid & 3;
            const uint32_t dst = ab + row * 64 + ((i ^ ((row >> 1) & 3)) << 4);
            const char* src = Ag + (size_t)row * 1024 + kb * 64 + i * 16;
            asm volatile("cp.async.cg.shared.global [%0], [%1], 16;"
                         :: "r"(dst), "l"(src) : "memory");
        }
        asm volatile("cp.async.commit_group;" ::: "memory");
    };

    float acc[4][8][4];
    #pragma unroll
    for (int mi = 0; mi < 4; ++mi)
        #pragma unroll
        for (int ni = 0; ni < 8; ++ni)
            #pragma unroll
            for (int e = 0; e < 4; ++e) acc[mi][ni][e] = 0.0f;

    issue_copy(0, 0);
    issue_copy(1, 1);

    #pragma unroll 1
    for (int it = 0; it < NIT; ++it) {
        const int stg = it % 3;
        // stage `it` ready: <=1 younger group may still be in flight, except
        // at the tail where no new commits arrive -> drain fully.
        if (it + 2 < NIT) asm volatile("cp.async.wait_group 1;" ::: "memory");
        else              asm volatile("cp.async.wait_group 0;" ::: "memory");
        __syncthreads();

        const uint32_t qb = sb + stg * STAGE_BYTES;
        const uint32_t ab = qb + 8192;

        uint32_t aq[4][2][4];
        #pragma unroll
        for (int mi = 0; mi < 4; ++mi)
            #pragma unroll
            for (int rr = 0; rr < 2; ++rr) {
                const int row = wm * 64 + mi * 16 + rr * 8 + g;
                const uint32_t addr = qb + row * 64 + ((tg ^ ((row >> 1) & 3)) << 4);
                asm volatile("ld.shared.v4.b32 {%0,%1,%2,%3}, [%4];"
                             : "=r"(aq[mi][rr][0]), "=r"(aq[mi][rr][1]),
                               "=r"(aq[mi][rr][2]), "=r"(aq[mi][rr][3])
                             : "r"(addr));
            }
        #pragma unroll
        for (int ni = 0; ni < 8; ++ni) {
            const int brow = wn * 64 + ni * 8 + g;
            const uint32_t baddr = ab + brow * 64 + ((tg ^ ((brow >> 1) & 3)) << 4);
            uint32_t b0, b1, b2, b3;
            asm volatile("ld.shared.v4.b32 {%0,%1,%2,%3}, [%4];"
                         : "=r"(b0), "=r"(b1), "=r"(b2), "=r"(b3) : "r"(baddr));
            #pragma unroll
            for (int mi = 0; mi < 4; ++mi) {
                // kstep0: a = rows {g, g+8} pairs k(2tg), k(2tg+8)
                mma_f16(acc[mi][ni],
                        aq[mi][0][0], aq[mi][1][0], aq[mi][0][1], aq[mi][1][1],
                        b0, b1);
                // kstep1: +16 halves
                mma_f16(acc[mi][ni],
                        aq[mi][0][2], aq[mi][1][2], aq[mi][0][3], aq[mi][1][3],
                        b2, b3);
            }
        }

        // refill the stage computed at it-1 (all threads passed this iter's
        // barrier after finishing it-1; (it+2)%3 == (it-1)%3 != it%3)
        if (it + 2 < NIT) issue_copy(it + 2, (it + 2) % 3);
    }

    // Epilogue: c0,c1 -> (row g, cols 2tg,2tg+1); c2,c3 -> row g+8.
    #pragma unroll
    for (int mi = 0; mi < 4; ++mi)
        #pragma unroll
        for (int rr = 0; rr < 2; ++rr) {
            const int row = mBase + wm * 64 + mi * 16 + rr * 8 + g;
            float* o = OUT + (size_t)row * DIM + nBase + wn * 64 + tg * 2;
            #pragma unroll
            for (int ni = 0; ni < 8; ++ni) {
                float2 v = make_float2(acc[mi][ni][rr * 2], acc[mi][ni][rr * 2 + 1]);
                *reinterpret_cast<float2*>(o + ni * 8) = v;
            }
        }
}

extern "C" void kernel_launch(void* const* d_in, const int* in_sizes, int n_in,
                              void* d_out, int out_size) {
    const float* P = (const float*)d_in[0];  // projected_input [4,4096,64]
    const float* W = (const float*)d_in[1];  // routing_weights [4,4096,8]
    const float* A = (const float*)d_in[2];  // A [8,4096,64] (pre-masked)
    // d_in[3] (sparse_mask) unused: A = A*mask already applied in setup;
    // mask is binary so re-masking is an exact no-op.
    (void)in_sizes; (void)n_in; (void)out_size;
    float* OUT = (float*)d_out;

    prep_q<<<TOK * 16 / 256, 256>>>(P, W);
    prep_a<<<DIM * 16 / 256, 256>>>(A);

    cudaFuncSetAttribute(lori_h16, cudaFuncAttributeMaxDynamicSharedMemorySize,
                         SMEM_BYTES);
    dim3 grid(DIM / BN, TOK / BM);   // (16, 128); x-fastest: AH + Q band L2-resident
    lori_h16<<<grid, 256, SMEM_BYTES>>>(OUT);
}

// round 15
// speedup vs baseline: 2.6607x; 1.1007x over previous
#include <cuda_runtime.h>
#include <cuda_fp16.h>
#include <cstdint>

// LoRIExpertBank as one NT GEMM, fp16 operands / fp32 accum (mma.m16n8k16).
//   out[t,d] = sum_c Q[t,c] * Aflat[d,c],  c = k*64+r,  Q[t,c] = w[t,k]*p[t,r]
// T=16384 (M), D=4096 (N), C=512 (K). SCALING = 64/64 = 1. A pre-masked in
// setup => sparse_mask ignored. fp16 mantissa (11 bit) == tf32 => accuracy
// matches the validated tf32 path (2.93e-4 measured). tcgen05 unavailable
// (harness PTX targets base sm_103).
//
// R14: same hypothesis as R10/R13 (R6 is issue-bound at 2 warps/SMSP) but via
// 2 CTAs/SM x 8 warps instead of one 16-warp CTA (that binary coincided with
// two container failures; avoid it). CTA tile 128x128, warp tile 32x64,
// acc 64 regs -> ~110 regs/thread, 48KB smem/CTA -> 2 CTAs/SM resident.

#define TOK 16384
#define DIM 4096
#define BM  128
#define BN  128
#define NIT 16
#define STAGE_BYTES 16384            // 8KB Q + 8KB A
#define SMEM_BYTES (3 * STAGE_BYTES) // 49152 = 48KB

// Operand buffers, fragment-permuted fp16. Row = 512 halves = 1024B = 64 uint4.
__device__ __align__(16) uint4 QH[(size_t)TOK * 64];   // 16 MB
__device__ __align__(16) uint4 AH[(size_t)DIM * 64];   //  4 MB

// Within each 32-half K-chunk, half-pair hp (0..15) is stored at slot
// pos = (hp&3)*4 + (hp>>2). Lane tg of an mma quad reads its whole k16x2
// fragment {hp = tg, tg+4, tg+8, tg+12} as ONE contiguous 16B chunk
// (chunk index = tg), XOR-swizzled by ((row>>1)&3).

__global__ void prep_q(const float* __restrict__ P,   // [TOK, 64]
                       const float* __restrict__ W) { // [TOK, 8]
    const int idx = blockIdx.x * 256 + threadIdx.x;   // TOK*16
    const int t  = idx >> 4;
    const int kb = idx & 15;                          // 32-half chunk
    const float w = W[t * 8 + (kb >> 1)];             // expert = kb/2
    const float4* src = reinterpret_cast<const float4*>(
        P + (size_t)t * 64 + (kb & 1) * 32);
    float f[32];
    #pragma unroll
    for (int i = 0; i < 8; ++i) {
        float4 v = src[i];
        f[i*4+0] = v.x; f[i*4+1] = v.y; f[i*4+2] = v.z; f[i*4+3] = v.w;
    }
    uint32_t o[16];
    #pragma unroll
    for (int pos = 0; pos < 16; ++pos) {
        const int hp = ((pos & 3) << 2) | (pos >> 2);
        __half2 h = __floats2half2_rn(w * f[2*hp], w * f[2*hp+1]);
        o[pos] = *reinterpret_cast<uint32_t*>(&h);
    }
    uint4* dst = QH + (size_t)t * 64 + kb * 4;
    dst[0] = make_uint4(o[0],  o[1],  o[2],  o[3]);
    dst[1] = make_uint4(o[4],  o[5],  o[6],  o[7]);
    dst[2] = make_uint4(o[8],  o[9],  o[10], o[11]);
    dst[3] = make_uint4(o[12], o[13], o[14], o[15]);
}

__global__ void prep_a(const float* __restrict__ A) { // [8, 4096, 64]
    const int idx = blockIdx.x * 256 + threadIdx.x;   // DIM*16
    const int d  = idx >> 4;
    const int kb = idx & 15;
    const float4* src = reinterpret_cast<const float4*>(
        A + ((size_t)(kb >> 1) * DIM + d) * 64 + (kb & 1) * 32);
    float f[32];
    #pragma unroll
    for (int i = 0; i < 8; ++i) {
        float4 v = src[i];
        f[i*4+0] = v.x; f[i*4+1] = v.y; f[i*4+2] = v.z; f[i*4+3] = v.w;
    }
    uint32_t o[16];
    #pragma unroll
    for (int pos = 0; pos < 16; ++pos) {
        const int hp = ((pos & 3) << 2) | (pos >> 2);
        __half2 h = __floats2half2_rn(f[2*hp], f[2*hp+1]);
        o[pos] = *reinterpret_cast<uint32_t*>(&h);
    }
    uint4* dst = AH + (size_t)d * 64 + kb * 4;
    dst[0] = make_uint4(o[0],  o[1],  o[2],  o[3]);
    dst[1] = make_uint4(o[4],  o[5],  o[6],  o[7]);
    dst[2] = make_uint4(o[8],  o[9],  o[10], o[11]);
    dst[3] = make_uint4(o[12], o[13], o[14], o[15]);
}

__device__ __forceinline__ void mma_f16(float c[4],
                                        uint32_t a0, uint32_t a1, uint32_t a2, uint32_t a3,
                                        uint32_t b0, uint32_t b1) {
    asm volatile(
        "mma.sync.aligned.m16n8k16.row.col.f32.f16.f16.f32 "
        "{%0,%1,%2,%3}, {%4,%5,%6,%7}, {%8,%9}, {%0,%1,%2,%3};"
        : "+f"(c[0]), "+f"(c[1]), "+f"(c[2]), "+f"(c[3])
        : "r"(a0), "r"(a1), "r"(a2), "r"(a3), "r"(b0), "r"(b1));
}

__global__ __launch_bounds__(256, 2)
void lori_h16(float* __restrict__ OUT) {
    extern __shared__ char smem[];
    const uint32_t sb = (uint32_t)__cvta_generic_to_shared(smem);
    const int tid  = threadIdx.x;
    const int lane = tid & 31;
    const int warp = tid >> 5;    // 0..7
    const int g  = lane >> 2;     // 0..7
    const int tg = lane & 3;      // 0..3
    const int wm = warp >> 1;     // 0..3 (M band of 32)
    const int wn = warp & 1;      // 0..1 (N band of 64)
    const int mBase = blockIdx.y * BM;
    const int nBase = blockIdx.x * BN;

    const char* Qg = reinterpret_cast<const char*>(QH) + (size_t)mBase * 1024;
    const char* Ag = reinterpret_cast<const char*>(AH) + (size_t)nBase * 1024;

    auto issue_copy = [&](int kb, int stg) {
        const uint32_t qb = sb + stg * STAGE_BYTES;
        const uint32_t ab = qb + 8192;
        // Q: 512 16B chunks (128 rows x 4) -> 2 per thread; A same.
        #pragma unroll
        for (int j = 0; j < 2; ++j) {
            const int cid = tid + j * 256;
            const int row = cid >> 2, i = cid & 3;
            const uint32_t soff = row * 64 + ((i ^ ((row >> 1) & 3)) << 4);
            const size_t goff = (size_t)row * 1024 + kb * 64 + i * 16;
            asm volatile("cp.async.cg.shared.global [%0], [%1], 16;"
                         :: "r"(qb + soff), "l"(Qg + goff) : "memory");
            asm volatile("cp.async.cg.shared.global [%0], [%1], 16;"
                         :: "r"(ab + soff), "l"(Ag + goff) : "memory");
        }
        asm volatile("cp.async.commit_group;" ::: "memory");
    };

    float acc[2][8][4];
    #pragma unroll
    for (int mi = 0; mi < 2; ++mi)
        #pragma unroll
        for (int ni = 0; ni < 8; ++ni)
            #pragma unroll
            for (int e = 0; e < 4; ++e) acc[mi][ni][e] = 0.0f;

    issue_copy(0, 0);
    issue_copy(1, 1);

    #pragma unroll 1
    for (int it = 0; it < NIT; ++it) {
        const int stg = it % 3;
        if (it + 2 < NIT) asm volatile("cp.async.wait_group 1;" ::: "memory");
        else              asm volatile("cp.async.wait_group 0;" ::: "memory");
        __syncthreads();

        const uint32_t qb = sb + stg * STAGE_BYTES;
        const uint32_t ab = qb + 8192;

        // Q fragments: warp's 32-row band, 2 mtiles x 2 rows, one LDS.128 each
        uint32_t aq[2][2][4];
        #pragma unroll
        for (int mi = 0; mi < 2; ++mi)
            #pragma unroll
            for (int rr = 0; rr < 2; ++rr) {
                const int row = wm * 32 + mi * 16 + rr * 8 + g;
                const uint32_t addr = qb + row * 64 + ((tg ^ ((row >> 1) & 3)) << 4);
                asm volatile("ld.shared.v4.b32 {%0,%1,%2,%3}, [%4];"
                             : "=r"(aq[mi][rr][0]), "=r"(aq[mi][rr][1]),
                               "=r"(aq[mi][rr][2]), "=r"(aq[mi][rr][3])
                             : "r"(addr));
            }
        #pragma unroll
        for (int ni = 0; ni < 8; ++ni) {
            const int brow = wn * 64 + ni * 8 + g;
            const uint32_t baddr = ab + brow * 64 + ((tg ^ ((brow >> 1) & 3)) << 4);
            uint32_t b0, b1, b2, b3;
            asm volatile("ld.shared.v4.b32 {%0,%1,%2,%3}, [%4];"
                         : "=r"(b0), "=r"(b1), "=r"(b2), "=r"(b3) : "r"(baddr));
            #pragma unroll
            for (int mi = 0; mi < 2; ++mi) {
                mma_f16(acc[mi][ni],
                        aq[mi][0][0], aq[mi][1][0], aq[mi][0][1], aq[mi][1][1],
                        b0, b1);
                mma_f16(acc[mi][ni],
                        aq[mi][0][2], aq[mi][1][2], aq[mi][0][3], aq[mi][1][3],
                        b2, b3);
            }
        }

        if (it + 2 < NIT) issue_copy(it + 2, (it + 2) % 3);
    }

    // Epilogue: c0,c1 -> (row g, cols 2tg,2tg+1); c2,c3 -> row g+8.
    #pragma unroll
    for (int mi = 0; mi < 2; ++mi)
        #pragma unroll
        for (int rr = 0; rr < 2; ++rr) {
            const int row = mBase + wm * 32 + mi * 16 + rr * 8 + g;
            float* o = OUT + (size_t)row * DIM + nBase + wn * 64 + tg * 2;
            #pragma unroll
            for (int ni = 0; ni < 8; ++ni) {
                float2 v = make_float2(acc[mi][ni][rr * 2], acc[mi][ni][rr * 2 + 1]);
                *reinterpret_cast<float2*>(o + ni * 8) = v;
            }
        }
}

extern "C" void kernel_launch(void* const* d_in, const int* in_sizes, int n_in,
                              void* d_out, int out_size) {
    const float* P = (const float*)d_in[0];  // projected_input [4,4096,64]
    const float* W = (const float*)d_in[1];  // routing_weights [4,4096,8]
    const float* A = (const float*)d_in[2];  // A [8,4096,64] (pre-masked)
    // d_in[3] (sparse_mask) unused: A = A*mask already applied in setup;
    // mask is binary so re-masking is an exact no-op.
    (void)in_sizes; (void)n_in; (void)out_size;
    float* OUT = (float*)d_out;

    prep_q<<<TOK * 16 / 256, 256>>>(P, W);
    prep_a<<<DIM * 16 / 256, 256>>>(A);

    cudaFuncSetAttribute(lori_h16, cudaFuncAttributeMaxDynamicSharedMemorySize,
                         SMEM_BYTES);
    dim3 grid(DIM / BN, TOK / BM);   // (32, 128); x-fastest: AH + Q band L2-resident
    lori_h16<<<grid, 256, SMEM_BYTES>>>(OUT);
}

// round 17
// speedup vs baseline: 2.6767x; 1.0060x over previous
#include <cuda_runtime.h>
#include <cuda_fp16.h>
#include <cstdint>

// LoRIExpertBank as one NT GEMM, fp16 operands / fp32 accum (mma.m16n8k16).
//   out[t,d] = sum_c Q[t,c] * Aflat[d,c],  c = k*64+r,  Q[t,c] = w[t,k]*p[t,r]
// T=16384 (M), D=4096 (N), C=512 (K). SCALING = 64/64 = 1. A pre-masked in
// setup => sparse_mask ignored. fp16 mantissa (11 bit) == tf32.
//
// Rate model (R1/R6/R14 cross-calibrated): sm_103a legacy mma.sync path is a
// flat ~512 MAC/cyc/SM for tf32-k8 AND f16-k16 => main GEMM floor ~239us; the
// R14 main loop is AT it (measured ~240us). tcgen05 unreachable (harness PTX
// is compute_103). R15: main kernel UNCHANGED; consolidate overhead only:
// single fused prep launch, prep_q restructured (smem-staged, P read 1x not 8x).

#define TOK 16384
#define DIM 4096
#define BM  128
#define BN  128
#define NIT 16
#define STAGE_BYTES 16384            // 8KB Q + 8KB A
#define SMEM_BYTES (3 * STAGE_BYTES) // 49152 = 48KB

// Operand buffers, fragment-permuted fp16. Row = 512 halves = 1024B = 64 uint4.
__device__ __align__(16) uint4 QH[(size_t)TOK * 64];   // 16 MB
__device__ __align__(16) uint4 AH[(size_t)DIM * 64];   //  4 MB

// Within each 32-half K-chunk, half-pair hp (0..15) is stored at slot
// pos = (hp&3)*4 + (hp>>2). Lane tg of an mma quad reads its whole k16x2
// fragment {hp = tg, tg+4, tg+8, tg+12} as ONE contiguous 16B chunk
// (chunk index = tg), XOR-swizzled by ((row>>1)&3).

#define QBLOCKS (TOK / 16)           // 1024 blocks for Q prep
#define ABLOCKS (DIM * 16 / 256)     // 256 blocks for A prep

__global__ void prep_all(const float* __restrict__ P,   // [TOK, 64]
                         const float* __restrict__ W,   // [TOK, 8]
                         const float* __restrict__ A) { // [8, 4096, 64]
    const int tid = threadIdx.x;
    if (blockIdx.x < QBLOCKS) {
        // ---- Q prep: 16 tokens per block, P staged through smem (read 1x) ----
        __shared__ float sP[16][64];
        __shared__ float sW[16][8];
        const int t0  = blockIdx.x * 16;
        const int tok = tid >> 4;
        const int kb  = tid & 15;
        // stage: one float4 of P per thread (coalesced), W by first 128 threads
        *reinterpret_cast<float4*>(&sP[tok][kb * 4]) =
            *reinterpret_cast<const float4*>(P + (size_t)(t0 + tok) * 64 + kb * 4);
        if (tid < 128) sW[tid >> 3][tid & 7] = W[t0 * 8 + tid];
        __syncthreads();

        const float w = sW[tok][kb >> 1];          // expert = kb/2
        const float* src = &sP[tok][(kb & 1) * 32];
        float f[32];
        #pragma unroll
        for (int i = 0; i < 8; ++i) {
            float4 v = *reinterpret_cast<const float4*>(src + i * 4);
            f[i*4+0] = v.x; f[i*4+1] = v.y; f[i*4+2] = v.z; f[i*4+3] = v.w;
        }
        uint32_t o[16];
        #pragma unroll
        for (int pos = 0; pos < 16; ++pos) {
            const int hp = ((pos & 3) << 2) | (pos >> 2);
            __half2 h = __floats2half2_rn(w * f[2*hp], w * f[2*hp+1]);
            o[pos] = *reinterpret_cast<uint32_t*>(&h);
        }
        uint4* dst = QH + (size_t)(t0 + tok) * 64 + kb * 4;   // 64B/thread, coalesced
        dst[0] = make_uint4(o[0],  o[1],  o[2],  o[3]);
        dst[1] = make_uint4(o[4],  o[5],  o[6],  o[7]);
        dst[2] = make_uint4(o[8],  o[9],  o[10], o[11]);
        dst[3] = make_uint4(o[12], o[13], o[14], o[15]);
    } else {
        // ---- A prep (4MB read once; unchanged logic) ----
        const int idx = (blockIdx.x - QBLOCKS) * 256 + tid;   // DIM*16
        const int d  = idx >> 4;
        const int kb = idx & 15;
        const float4* src = reinterpret_cast<const float4*>(
            A + ((size_t)(kb >> 1) * DIM + d) * 64 + (kb & 1) * 32);
        float f[32];
        #pragma unroll
        for (int i = 0; i < 8; ++i) {
            float4 v = src[i];
            f[i*4+0] = v.x; f[i*4+1] = v.y; f[i*4+2] = v.z; f[i*4+3] = v.w;
        }
        uint32_t o[16];
        #pragma unroll
        for (int pos = 0; pos < 16; ++pos) {
            const int hp = ((pos & 3) << 2) | (pos >> 2);
            __half2 h = __floats2half2_rn(f[2*hp], f[2*hp+1]);
            o[pos] = *reinterpret_cast<uint32_t*>(&h);
        }
        uint4* dst = AH + (size_t)d * 64 + kb * 4;
        dst[0] = make_uint4(o[0],  o[1],  o[2],  o[3]);
        dst[1] = make_uint4(o[4],  o[5],  o[6],  o[7]);
        dst[2] = make_uint4(o[8],  o[9],  o[10], o[11]);
        dst[3] = make_uint4(o[12], o[13], o[14], o[15]);
    }
}

__device__ __forceinline__ void mma_f16(float c[4],
                                        uint32_t a0, uint32_t a1, uint32_t a2, uint32_t a3,
                                        uint32_t b0, uint32_t b1) {
    asm volatile(
        "mma.sync.aligned.m16n8k16.row.col.f32.f16.f16.f32 "
        "{%0,%1,%2,%3}, {%4,%5,%6,%7}, {%8,%9}, {%0,%1,%2,%3};"
        : "+f"(c[0]), "+f"(c[1]), "+f"(c[2]), "+f"(c[3])
        : "r"(a0), "r"(a1), "r"(a2), "r"(a3), "r"(b0), "r"(b1));
}

__global__ __launch_bounds__(256, 2)
void lori_h16(float* __restrict__ OUT) {
    extern __shared__ char smem[];
    const uint32_t sb = (uint32_t)__cvta_generic_to_shared(smem);
    const int tid  = threadIdx.x;
    const int lane = tid & 31;
    const int warp = tid >> 5;    // 0..7
    const int g  = lane >> 2;     // 0..7
    const int tg = lane & 3;      // 0..3
    const int wm = warp >> 1;     // 0..3 (M band of 32)
    const int wn = warp & 1;      // 0..1 (N band of 64)
    const int mBase = blockIdx.y * BM;
    const int nBase = blockIdx.x * BN;

    const char* Qg = reinterpret_cast<const char*>(QH) + (size_t)mBase * 1024;
    const char* Ag = reinterpret_cast<const char*>(AH) + (size_t)nBase * 1024;

    auto issue_copy = [&](int kb, int stg) {
        const uint32_t qb = sb + stg * STAGE_BYTES;
        const uint32_t ab = qb + 8192;
        // Q: 512 16B chunks (128 rows x 4) -> 2 per thread; A same.
        #pragma unroll
        for (int j = 0; j < 2; ++j) {
            const int cid = tid + j * 256;
            const int row = cid >> 2, i = cid & 3;
            const uint32_t soff = row * 64 + ((i ^ ((row >> 1) & 3)) << 4);
            const size_t goff = (size_t)row * 1024 + kb * 64 + i * 16;
            asm volatile("cp.async.cg.shared.global [%0], [%1], 16;"
                         :: "r"(qb + soff), "l"(Qg + goff) : "memory");
            asm volatile("cp.async.cg.shared.global [%0], [%1], 16;"
                         :: "r"(ab + soff), "l"(Ag + goff) : "memory");
        }
        asm volatile("cp.async.commit_group;" ::: "memory");
    };

    float acc[2][8][4];
    #pragma unroll
    for (int mi = 0; mi < 2; ++mi)
        #pragma unroll
        for (int ni = 0; ni < 8; ++ni)
            #pragma unroll
            for (int e = 0; e < 4; ++e) acc[mi][ni][e] = 0.0f;

    issue_copy(0, 0);
    issue_copy(1, 1);

    #pragma unroll 1
    for (int it = 0; it < NIT; ++it) {
        const int stg = it % 3;
        if (it + 2 < NIT) asm volatile("cp.async.wait_group 1;" ::: "memory");
        else              asm volatile("cp.async.wait_group 0;" ::: "memory");
        __syncthreads();

        const uint32_t qb = sb + stg * STAGE_BYTES;
        const uint32_t ab = qb + 8192;

        // Q fragments: warp's 32-row band, 2 mtiles x 2 rows, one LDS.128 each
        uint32_t aq[2][2][4];
        #pragma unroll
        for (int mi = 0; mi < 2; ++mi)
            #pragma unroll
            for (int rr = 0; rr < 2; ++rr) {
                const int row = wm * 32 + mi * 16 + rr * 8 + g;
                const uint32_t addr = qb + row * 64 + ((tg ^ ((row >> 1) & 3)) << 4);
                asm volatile("ld.shared.v4.b32 {%0,%1,%2,%3}, [%4];"
                             : "=r"(aq[mi][rr][0]), "=r"(aq[mi][rr][1]),
                               "=r"(aq[mi][rr][2]), "=r"(aq[mi][rr][3])
                             : "r"(addr));
            }
        #pragma unroll
        for (int ni = 0; ni < 8; ++ni) {
            const int brow = wn * 64 + ni * 8 + g;
            const uint32_t baddr = ab + brow * 64 + ((tg ^ ((brow >> 1) & 3)) << 4);
            uint32_t b0, b1, b2, b3;
            asm volatile("ld.shared.v4.b32 {%0,%1,%2,%3}, [%4];"
                         : "=r"(b0), "=r"(b1), "=r"(b2), "=r"(b3) : "r"(baddr));
            #pragma unroll
            for (int mi = 0; mi < 2; ++mi) {
                mma_f16(acc[mi][ni],
                        aq[mi][0][0], aq[mi][1][0], aq[mi][0][1], aq[mi][1][1],
                        b0, b1);
                mma_f16(acc[mi][ni],
                        aq[mi][0][2], aq[mi][1][2], aq[mi][0][3], aq[mi][1][3],
                        b2, b3);
            }
        }

        if (it + 2 < NIT) issue_copy(it + 2, (it + 2) % 3);
    }

    // Epilogue: c0,c1 -> (row g, cols 2tg,2tg+1); c2,c3 -> row g+8.
    #pragma unroll
    for (int mi = 0; mi < 2; ++mi)
        #pragma unroll
        for (int rr = 0; rr < 2; ++rr) {
            const int row = mBase + wm * 32 + mi * 16 + rr * 8 + g;
            float* o = OUT + (size_t)row * DIM + nBase + wn * 64 + tg * 2;
            #pragma unroll
            for (int ni = 0; ni < 8; ++ni) {
                float2 v = make_float2(acc[mi][ni][rr * 2], acc[mi][ni][rr * 2 + 1]);
                *reinterpret_cast<float2*>(o + ni * 8) = v;
            }
        }
}

extern "C" void kernel_launch(void* const* d_in, const int* in_sizes, int n_in,
                              void* d_out, int out_size) {
    const float* P = (const float*)d_in[0];  // projected_input [4,4096,64]
    const float* W = (const float*)d_in[1];  // routing_weights [4,4096,8]
    const float* A = (const float*)d_in[2];  // A [8,4096,64] (pre-masked)
    // d_in[3] (sparse_mask) unused: A = A*mask already applied in setup;
    // mask is binary so re-masking is an exact no-op.
    (void)in_sizes; (void)n_in; (void)out_size;
    float* OUT = (float*)d_out;

    prep_all<<<QBLOCKS + ABLOCKS, 256>>>(P, W, A);

    cudaFuncSetAttribute(lori_h16, cudaFuncAttributeMaxDynamicSharedMemorySize,
                         SMEM_BYTES);
    dim3 grid(DIM / BN, TOK / BM);   // (32, 128); x-fastest: AH + Q band L2-resident
    lori_h16<<<grid, 256, SMEM_BYTES>>>(OUT);
}